// round 5
// baseline (speedup 1.0000x reference)
#include <cuda_runtime.h>

// inputs [4,320,320,2] f32 -> output [4,320,320,6] f32
#define NB   4
#define NH   320
#define NW   320
#define NIMG 8

// Scratch: per-image squared 1D column distances g2[img][h][w].
__device__ float g2_scratch[NIMG * NH * NW];

// -------------------------------------------------------------------------
// Kernel 1: column pass, segmented for parallelism.
// grid (NIMG, NW/32), block (32, 10): 32 columns x 10 row-segments of 32.
// Phase A: per-thread local scan of 32 rows -> per-row local last-seed (smem),
//          per-segment last/first seed.
// Phase B: 10-wide prefix(max)/suffix(min) across segments (seg-0 threads).
// Phase C: per-thread backward scan of its segment, write g2 to global.
// Seed: uint8((1-x)*127.5) == 0  <=>  (1-x)*127.5 < 1.
// Sentinels (-32768 / 20000) give g ~ 2e4..3.3e4: g^2 >= 4e8, exp underflows
// to exactly 0 for all sigmas and can never beat a real candidate, matching
// the reference's BIG=1e5 behavior.
// -------------------------------------------------------------------------
#define CW   32
#define NSEG 10
#define SEGH 32

__global__ void __launch_bounds__(CW * NSEG) col_pass_kernel(const float* __restrict__ in) {
    __shared__ short smLast[NH][CW];      // 20 KB
    __shared__ short segLast[NSEG][CW];
    __shared__ short segFirst[NSEG][CW];
    __shared__ short incLast[NSEG][CW];
    __shared__ short incNxt[NSEG][CW];

    const int img = blockIdx.x;           // 0..7
    const int b   = img >> 1;
    const int c   = img & 1;
    const int wt  = threadIdx.x;          // 0..31
    const int seg = threadIdx.y;          // 0..9
    const int w   = blockIdx.y * CW + wt;
    const int h0  = seg * SEGH;

    const float* __restrict__ base = in + (((size_t)b * NH) * NW + w) * 2 + c;

    // Phase A: batched loads (MLP=32), local forward scan.
    float v[SEGH];
    #pragma unroll
    for (int u = 0; u < SEGH; ++u)
        v[u] = base[(size_t)(h0 + u) * (NW * 2)];

    int last = -32768, first = 20000;
    #pragma unroll
    for (int u = 0; u < SEGH; ++u) {
        int h = h0 + u;
        if ((1.0f - v[u]) * 127.5f < 1.0f) {
            last = h;
            if (first == 20000) first = h;
        }
        smLast[h][wt] = (short)last;
    }
    segLast[seg][wt]  = (short)last;
    segFirst[seg][wt] = (short)first;
    __syncthreads();

    // Phase B: cross-segment prefix(max of last) / suffix(min of first).
    if (seg == 0) {
        int acc = -32768;
        #pragma unroll
        for (int s = 0; s < NSEG; ++s) {
            incLast[s][wt] = (short)acc;
            acc = max(acc, (int)segLast[s][wt]);
        }
        int acc2 = 20000;
        #pragma unroll
        for (int s = NSEG - 1; s >= 0; --s) {
            incNxt[s][wt] = (short)acc2;
            acc2 = min(acc2, (int)segFirst[s][wt]);
        }
    }
    __syncthreads();

    // Phase C: backward scan within segment, write g2.
    float* __restrict__ sc = g2_scratch + (size_t)img * NH * NW + w;
    const int inc = incLast[seg][wt];
    int nxt = incNxt[seg][wt];
    #pragma unroll
    for (int u = SEGH - 1; u >= 0; --u) {
        int h = h0 + u;
        int lastv = max((int)smLast[h][wt], inc);
        if (lastv == h) nxt = h;
        float g = (float)min(h - lastv, nxt - h);
        sc[(size_t)h * NW] = g * g;
    }
}

// -------------------------------------------------------------------------
// Kernel 2: row pass, one thread per (pixel j, channel). Exact pruned
// outward search with per-thread bound (tighter than shared max over 2 ch).
// grid NB*NH, block 640.
// -------------------------------------------------------------------------
__global__ void __launch_bounds__(2 * NW) row_pass_kernel(float* __restrict__ out) {
    const int bh = blockIdx.x;            // b*320 + h
    const int b  = bh / NH;
    const int h  = bh - b * NH;
    const int t  = threadIdx.x;           // 0..639
    const int ch = (t >= NW) ? 1 : 0;
    const int j  = t - ch * NW;

    __shared__ __align__(16) float sh[2][NW];

    // Cooperative load of both channel rows (640 threads, 640 floats).
    {
        const float* __restrict__ src =
            g2_scratch + (((size_t)(b * 2 + ch) * NH) + h) * NW;
        sh[ch][j] = src[j];
    }
    __syncthreads();

    const float4* __restrict__ vv = (const float4*)sh[ch];
    const float fj = (float)j;
    float m = 3e38f;

    auto evalTile = [&](int tb) {
        float4 a = vv[tb];
        float d0 = fj - (float)(tb * 4);
        float d1 = d0 - 1.0f;
        float d2 = d0 - 2.0f;
        float d3 = d0 - 3.0f;
        m = fminf(m, fmaf(d0, d0, a.x));
        m = fminf(m, fmaf(d1, d1, a.y));
        m = fminf(m, fmaf(d2, d2, a.z));
        m = fminf(m, fmaf(d3, d3, a.w));
    };

    const int tb0 = j >> 2;
    evalTile(tb0);

    int tl = tb0 - 1;
    int tr = tb0 + 1;
    float dL = fj - (float)(4 * tl + 3);  // min distance into left tile
    float dR = (float)(4 * tr) - fj;      // min distance into right tile
    bool doneL = (tl < 0);
    bool doneR = (tr >= NW / 4);

    while (!(doneL && doneR)) {
        if (!doneL) {
            if (dL * dL > m) {
                doneL = true;
            } else {
                evalTile(tl);
                --tl; dL += 4.0f;
                doneL = (tl < 0);
            }
        }
        if (!doneR) {
            if (dR * dR > m) {
                doneR = true;
            } else {
                evalTile(tr);
                ++tr; dR += 4.0f;
                doneR = (tr >= NW / 4);
            }
        }
    }

    // sigmas = [0.02,0.08,0.16]*320 -> 2*sigma^2 = [81.92, 1310.72, 5242.88]
    const float inv0 = 1.0f / 81.92f;
    const float inv1 = 1.0f / 1310.72f;
    const float inv2 = 1.0f / 5242.88f;

    float* __restrict__ o = out + ((size_t)bh * NW + j) * 6 + ch * 3;
    o[0] = __expf(-m * inv0);
    o[1] = __expf(-m * inv1);
    o[2] = __expf(-m * inv2);
}

extern "C" void kernel_launch(void* const* d_in, const int* in_sizes, int n_in,
                              void* d_out, int out_size) {
    const float* in = (const float*)d_in[0];
    float* out = (float*)d_out;
    (void)in_sizes; (void)n_in; (void)out_size;

    dim3 g1(NIMG, NW / CW);
    dim3 b1(CW, NSEG);
    col_pass_kernel<<<g1, b1>>>(in);
    row_pass_kernel<<<NB * NH, 2 * NW>>>(out);
}

// round 6
// speedup vs baseline: 1.8546x; 1.8546x over previous
#include <cuda_runtime.h>

// inputs [4,320,320,2] f32 -> output [4,320,320,6] f32
#define NB   4
#define NH   320
#define NW   320
#define NIMG 8

// Scratch: per-image squared 1D column distances g2[img][h][w].
__device__ float g2_scratch[NIMG * NH * NW];

// -------------------------------------------------------------------------
// Kernel 1: column pass, segmented for parallelism (kept from R5 - it won).
// grid (NIMG, NW/32), block (32, 10): 32 columns x 10 row-segments of 32.
// Sentinels (-32768 / 20000) give g^2 >= 4e8: exp underflows to exactly 0
// for all sigmas and can never beat a real candidate -> matches BIG=1e5.
// -------------------------------------------------------------------------
#define CW   32
#define NSEG 10
#define SEGH 32

__global__ void __launch_bounds__(CW * NSEG) col_pass_kernel(const float* __restrict__ in) {
    __shared__ short smLast[NH][CW];      // 20 KB
    __shared__ short segLast[NSEG][CW];
    __shared__ short segFirst[NSEG][CW];
    __shared__ short incLast[NSEG][CW];
    __shared__ short incNxt[NSEG][CW];

    const int img = blockIdx.x;           // 0..7
    const int b   = img >> 1;
    const int c   = img & 1;
    const int wt  = threadIdx.x;          // 0..31
    const int seg = threadIdx.y;          // 0..9
    const int w   = blockIdx.y * CW + wt;
    const int h0  = seg * SEGH;

    const float* __restrict__ base = in + (((size_t)b * NH) * NW + w) * 2 + c;

    // Phase A: batched loads (MLP=32), local forward scan.
    float v[SEGH];
    #pragma unroll
    for (int u = 0; u < SEGH; ++u)
        v[u] = base[(size_t)(h0 + u) * (NW * 2)];

    int last = -32768, first = 20000;
    #pragma unroll
    for (int u = 0; u < SEGH; ++u) {
        int h = h0 + u;
        if ((1.0f - v[u]) * 127.5f < 1.0f) {
            last = h;
            if (first == 20000) first = h;
        }
        smLast[h][wt] = (short)last;
    }
    segLast[seg][wt]  = (short)last;
    segFirst[seg][wt] = (short)first;
    __syncthreads();

    // Phase B: cross-segment prefix(max of last) / suffix(min of first).
    if (seg == 0) {
        int acc = -32768;
        #pragma unroll
        for (int s = 0; s < NSEG; ++s) {
            incLast[s][wt] = (short)acc;
            acc = max(acc, (int)segLast[s][wt]);
        }
        int acc2 = 20000;
        #pragma unroll
        for (int s = NSEG - 1; s >= 0; --s) {
            incNxt[s][wt] = (short)acc2;
            acc2 = min(acc2, (int)segFirst[s][wt]);
        }
    }
    __syncthreads();

    // Phase C: backward scan within segment, write g2.
    float* __restrict__ sc = g2_scratch + (size_t)img * NH * NW + w;
    const int inc = incLast[seg][wt];
    int nxt = incNxt[seg][wt];
    #pragma unroll
    for (int u = SEGH - 1; u >= 0; --u) {
        int h = h0 + u;
        int lastv = max((int)smLast[h][wt], inc);
        if (lastv == h) nxt = h;
        float g = (float)min(h - lastv, nxt - h);
        sc[(size_t)h * NW] = g * g;
    }
}

// -------------------------------------------------------------------------
// Kernel 2: row pass. One thread per pixel j, BOTH channels (shared loop
// control). Exact pruned outward search over 8-wide column tiles.
// grid NB*NH, block 320.
// -------------------------------------------------------------------------
#define NT8 (NW / 8)   // 40 tiles of 8 columns

__global__ void __launch_bounds__(NW) row_pass_kernel(float* __restrict__ out) {
    const int bh = blockIdx.x;            // b*320 + h
    const int j  = threadIdx.x;
    const int b  = bh / NH;
    const int h  = bh - b * NH;

    __shared__ __align__(16) float sh0[NW];
    __shared__ __align__(16) float sh1[NW];

    sh0[j] = g2_scratch[(((size_t)(b * 2 + 0) * NH) + h) * NW + j];
    sh1[j] = g2_scratch[(((size_t)(b * 2 + 1) * NH) + h) * NW + j];
    __syncthreads();

    const float4* __restrict__ v0 = (const float4*)sh0;
    const float4* __restrict__ v1 = (const float4*)sh1;

    const float fj = (float)j;
    float m0 = 3e38f, m1 = 3e38f;

    // Evaluate one 8-wide tile (tb in [0,40)) for both channels.
    // Tree-reduced mins to shorten the dependent chain.
    auto evalTile8 = [&](int tb) {
        float4 a0 = v0[2 * tb];
        float4 a1 = v0[2 * tb + 1];
        float4 c0 = v1[2 * tb];
        float4 c1 = v1[2 * tb + 1];
        float d0 = fj - (float)(tb * 8);
        float d1 = d0 - 1.0f, d2 = d0 - 2.0f, d3 = d0 - 3.0f;
        float d4 = d0 - 4.0f, d5 = d0 - 5.0f, d6 = d0 - 6.0f, d7 = d0 - 7.0f;

        float r0 = fmaf(d0, d0, a0.x), r1 = fmaf(d1, d1, a0.y);
        float r2 = fmaf(d2, d2, a0.z), r3 = fmaf(d3, d3, a0.w);
        float r4 = fmaf(d4, d4, a1.x), r5 = fmaf(d5, d5, a1.y);
        float r6 = fmaf(d6, d6, a1.z), r7 = fmaf(d7, d7, a1.w);
        float t0 = fminf(r0, r1), t1 = fminf(r2, r3);
        float t2 = fminf(r4, r5), t3 = fminf(r6, r7);
        m0 = fminf(m0, fminf(fminf(t0, t1), fminf(t2, t3)));

        float s0 = fmaf(d0, d0, c0.x), s1 = fmaf(d1, d1, c0.y);
        float s2 = fmaf(d2, d2, c0.z), s3 = fmaf(d3, d3, c0.w);
        float s4 = fmaf(d4, d4, c1.x), s5 = fmaf(d5, d5, c1.y);
        float s6 = fmaf(d6, d6, c1.z), s7 = fmaf(d7, d7, c1.w);
        float u0 = fminf(s0, s1), u1 = fminf(s2, s3);
        float u2 = fminf(s4, s5), u3 = fminf(s6, s7);
        m1 = fminf(m1, fminf(fminf(u0, u1), fminf(u2, u3)));
    };

    const int tb0 = j >> 3;
    evalTile8(tb0);

    int tl = tb0 - 1;
    int tr = tb0 + 1;
    float dL = fj - (float)(8 * tl + 7);  // min distance into left tile
    float dR = (float)(8 * tr) - fj;      // min distance into right tile

    for (;;) {
        float mM = fmaxf(m0, m1);
        bool needL = (tl >= 0)  && (dL * dL <= mM);
        bool needR = (tr < NT8) && (dR * dR <= mM);
        if (!(needL || needR)) break;
        if (needL) { evalTile8(tl); --tl; dL += 8.0f; }
        if (needR) { evalTile8(tr); ++tr; dR += 8.0f; }
    }

    // sigmas = [0.02,0.08,0.16]*320 -> 2*sigma^2 = [81.92, 1310.72, 5242.88]
    const float inv0 = 1.0f / 81.92f;
    const float inv1 = 1.0f / 1310.72f;
    const float inv2 = 1.0f / 5242.88f;

    float* __restrict__ o = out + ((size_t)bh * NW + j) * 6;
    float2 p0 = make_float2(__expf(-m0 * inv0), __expf(-m0 * inv1));
    float2 p1 = make_float2(__expf(-m0 * inv2), __expf(-m1 * inv0));
    float2 p2 = make_float2(__expf(-m1 * inv1), __expf(-m1 * inv2));
    ((float2*)o)[0] = p0;
    ((float2*)o)[1] = p1;
    ((float2*)o)[2] = p2;
}

extern "C" void kernel_launch(void* const* d_in, const int* in_sizes, int n_in,
                              void* d_out, int out_size) {
    const float* in = (const float*)d_in[0];
    float* out = (float*)d_out;
    (void)in_sizes; (void)n_in; (void)out_size;

    dim3 g1(NIMG, NW / CW);
    dim3 b1(CW, NSEG);
    col_pass_kernel<<<g1, b1>>>(in);
    row_pass_kernel<<<NB * NH, NW>>>(out);
}